// round 3
// baseline (speedup 1.0000x reference)
#include <cuda_runtime.h>
#include <cuda_bf16.h>
#include <cstdint>

// Embedding gather: out[t, :] = weight[token_ids[t], :]
// d_in[0] = token_ids (int32), 8192 elements  [B=4, S=2048]
// d_in[1] = weight (float32), 32000 x 1024
// d_out   = float32, 8192 x 1024
//
// MLP-optimized: 8 tokens per CTA, 256 threads. Each thread:
//   - loads 8 token ids (uniform broadcast, independent)
//   - issues 8 independent LDG.128 gathers (front-batched, MLP=8)
//   - 8 STG.128 stores
// Row = 1024 floats = 256 float4 => thread tid handles float4 chunk tid of
// each of the 8 rows.

static constexpr int D4 = 256;          // float4s per row
static constexpr int THREADS = 256;
static constexpr int TOK_PER_CTA = 8;

__global__ __launch_bounds__(THREADS)
void embedding_gather_kernel(const int* __restrict__ token_ids,
                             const float4* __restrict__ weight,
                             float4* __restrict__ out,
                             int n_tokens) {
    const int t_base = blockIdx.x * TOK_PER_CTA;
    const int tid = threadIdx.x;

    // Front-batched independent index loads (uniform across the CTA).
    int rows[TOK_PER_CTA];
#pragma unroll
    for (int i = 0; i < TOK_PER_CTA; ++i) {
        rows[i] = __ldg(token_ids + t_base + i);
    }

    // Front-batched independent gather loads: MLP = 8 per thread.
    float4 v[TOK_PER_CTA];
#pragma unroll
    for (int i = 0; i < TOK_PER_CTA; ++i) {
        v[i] = __ldg(weight + (size_t)rows[i] * D4 + tid);
    }

    // Streaming stores.
    float4* dst = out + (size_t)t_base * D4 + tid;
#pragma unroll
    for (int i = 0; i < TOK_PER_CTA; ++i) {
        dst[(size_t)i * D4] = v[i];
    }
}

extern "C" void kernel_launch(void* const* d_in, const int* in_sizes, int n_in,
                              void* d_out, int out_size) {
    const int* token_ids = (const int*)d_in[0];
    const float4* weight = (const float4*)d_in[1];
    float4* out = (float4*)d_out;

    int n_tokens = in_sizes[0];            // 8192
    int n_ctas = n_tokens / TOK_PER_CTA;   // 1024

    embedding_gather_kernel<<<n_ctas, THREADS>>>(token_ids, weight, out, n_tokens);
}